// round 2
// baseline (speedup 1.0000x reference)
#include <cuda_runtime.h>
#include <math.h>

#define BATCH 256
#define TSTEPS 512
#define IDIM 64
#define HDIM 512
#define BB 16               // batch rows per CTA
#define BJ 64               // h columns per CTA
#define NBB (BATCH / BB)    // 16
#define NJB (HDIM / BJ)     // 8
#define NCTAS (NBB * NJB)   // 128  (<= 148 SMs -> co-resident, spin barrier safe)
#define THREADS 256

#define HPAD 516            // 512 + 4 : break bank alignment between rows
#define XPAD 68             // 64 + 4

// smem layout (floats): Whh[512*64] | Wxh[64*64] | h[16*516] | x[16*68]
#define SM_WHH   0
#define SM_WXH   (SM_WHH + HDIM * BJ)
#define SM_H     (SM_WXH + IDIM * BJ)
#define SM_X     (SM_H + BB * HPAD)
#define SM_FLOATS (SM_X + BB * XPAD)
#define SMEM_BYTES (SM_FLOATS * 4)

// scratch: double-buffered hidden state (1 MB) + barrier state
__device__ float    g_h[2][BATCH * HDIM];
__device__ unsigned g_bar_count;
__device__ unsigned g_bar_gen;

__device__ __forceinline__ void grid_sync() {
    __syncthreads();
    if (threadIdx.x == 0) {
        __threadfence();                         // release: publish h writes
        unsigned old_gen = *((volatile unsigned*)&g_bar_gen);
        unsigned arrived = atomicAdd(&g_bar_count, 1u);
        if (arrived == NCTAS - 1) {
            g_bar_count = 0;                     // safe: nobody arrives for next
            __threadfence();                     // barrier until gen bumps
            atomicAdd(&g_bar_gen, 1u);
        } else {
            while (*((volatile unsigned*)&g_bar_gen) == old_gen) {
                __nanosleep(32);
            }
        }
        __threadfence();                         // acquire
    }
    __syncthreads();
}

extern __shared__ float smem[];

__global__ void __launch_bounds__(THREADS, 1)
rnn_persistent_kernel(const float* __restrict__ x,
                      const float* __restrict__ W_xh,
                      const float* __restrict__ W_hh,
                      const float* __restrict__ bias,
                      const float* __restrict__ fc_w,
                      const float* __restrict__ fc_b,
                      float* __restrict__ out)
{
    float* s_Whh = smem + SM_WHH;
    float* s_Wxh = smem + SM_WXH;
    float* s_h   = smem + SM_H;
    float* s_x   = smem + SM_X;

    const int tid = threadIdx.x;
    const int tx  = tid & 15;       // j group (4 cols each)
    const int ty  = tid >> 4;       // batch row within tile
    const int bb  = blockIdx.x & (NBB - 1);
    const int jb  = blockIdx.x >> 4;
    const int b0  = bb * BB;
    const int j0  = jb * BJ;

    // ---- load persistent weight tiles into smem ----
    // W_hh slice: rows k=0..511, cols j0..j0+63   (128 KB)
    for (int idx = tid; idx < HDIM * BJ / 4; idx += THREADS) {
        int k = idx >> 4;            // 16 float4 per row
        int c = idx & 15;
        ((float4*)s_Whh)[idx] = *(const float4*)&W_hh[k * HDIM + j0 + c * 4];
    }
    // W_xh slice: rows i=0..63, cols j0..j0+63    (16 KB)
    for (int idx = tid; idx < IDIM * BJ / 4; idx += THREADS) {
        int i = idx >> 4;
        int c = idx & 15;
        ((float4*)s_Wxh)[idx] = *(const float4*)&W_xh[i * HDIM + j0 + c * 4];
    }
    // per-thread bias for its 4 output columns
    float4 rb = *(const float4*)&bias[j0 + tx * 4];

    // ---- zero h_0 (each CTA owns disjoint [b0:b0+16, j0:j0+64] slice) ----
    for (int idx = tid; idx < BB * BJ / 4; idx += THREADS) {
        int r = idx >> 4;
        int c = idx & 15;
        *(float4*)&g_h[0][(b0 + r) * HDIM + j0 + c * 4] = make_float4(0.f, 0.f, 0.f, 0.f);
    }
    grid_sync();

    int p = 0;
    for (int t = 0; t < TSTEPS; ++t) {
        // load x[b0:b0+16, t, :] tile (16x64): exactly one float4 per thread
        {
            int r = tid >> 4;
            int c = tid & 15;
            *(float4*)&s_x[r * XPAD + c * 4] =
                *(const float4*)&x[((b0 + r) * TSTEPS + t) * IDIM + c * 4];
        }
        // load h_prev[b0:b0+16, :] full rows (16x512 = 2048 float4)
        {
            const float* hsrc = g_h[p];
            for (int idx = tid; idx < BB * HDIM / 4; idx += THREADS) {
                int r = idx >> 7;
                int c = idx & 127;
                *(float4*)&s_h[r * HPAD + c * 4] =
                    *(const float4*)&hsrc[(b0 + r) * HDIM + c * 4];
            }
        }
        __syncthreads();

        float4 acc = rb;

        // xh contribution: acc += x[b,:] @ Wxh[:, j..j+3]
        {
            const float* xrow = &s_x[ty * XPAD];
            const float* wb   = s_Wxh + tx * 4;
            #pragma unroll
            for (int i = 0; i < IDIM; i += 4) {
                float4 xv = *(const float4*)&xrow[i];
                float4 w0 = *(const float4*)&wb[(i + 0) * BJ];
                acc.x += xv.x * w0.x; acc.y += xv.x * w0.y;
                acc.z += xv.x * w0.z; acc.w += xv.x * w0.w;
                float4 w1 = *(const float4*)&wb[(i + 1) * BJ];
                acc.x += xv.y * w1.x; acc.y += xv.y * w1.y;
                acc.z += xv.y * w1.z; acc.w += xv.y * w1.w;
                float4 w2 = *(const float4*)&wb[(i + 2) * BJ];
                acc.x += xv.z * w2.x; acc.y += xv.z * w2.y;
                acc.z += xv.z * w2.z; acc.w += xv.z * w2.w;
                float4 w3 = *(const float4*)&wb[(i + 3) * BJ];
                acc.x += xv.w * w3.x; acc.y += xv.w * w3.y;
                acc.z += xv.w * w3.z; acc.w += xv.w * w3.w;
            }
        }
        // recurrence: acc += h[b,:] @ Whh[:, j..j+3]
        {
            const float* hrow = &s_h[ty * HPAD];
            const float* wb   = s_Whh + tx * 4;
            #pragma unroll 4
            for (int k = 0; k < HDIM; k += 4) {
                float4 hv = *(const float4*)&hrow[k];
                float4 w0 = *(const float4*)&wb[(k + 0) * BJ];
                acc.x += hv.x * w0.x; acc.y += hv.x * w0.y;
                acc.z += hv.x * w0.z; acc.w += hv.x * w0.w;
                float4 w1 = *(const float4*)&wb[(k + 1) * BJ];
                acc.x += hv.y * w1.x; acc.y += hv.y * w1.y;
                acc.z += hv.y * w1.z; acc.w += hv.y * w1.w;
                float4 w2 = *(const float4*)&wb[(k + 2) * BJ];
                acc.x += hv.z * w2.x; acc.y += hv.z * w2.y;
                acc.z += hv.z * w2.z; acc.w += hv.z * w2.w;
                float4 w3 = *(const float4*)&wb[(k + 3) * BJ];
                acc.x += hv.w * w3.x; acc.y += hv.w * w3.y;
                acc.z += hv.w * w3.z; acc.w += hv.w * w3.w;
            }
        }

        float4 hn;
        hn.x = tanhf(acc.x);
        hn.y = tanhf(acc.y);
        hn.z = tanhf(acc.z);
        hn.w = tanhf(acc.w);
        *(float4*)&g_h[p ^ 1][(b0 + ty) * HDIM + j0 + tx * 4] = hn;

        p ^= 1;
        grid_sync();
    }

    // ---- final projection: out[b] = h_final[b,:] . fc_w + fc_b, by jb==0 CTAs ----
    if (jb == 0) {
        const float* hrow = &g_h[p][(b0 + ty) * HDIM];
        float s = 0.f;
        for (int c = tx; c < HDIM / 4; c += 16) {
            float4 hv = ((const float4*)hrow)[c];
            float4 wv = *(const float4*)&fc_w[c * 4];
            s += hv.x * wv.x + hv.y * wv.y + hv.z * wv.z + hv.w * wv.w;
        }
        #pragma unroll
        for (int off = 8; off; off >>= 1)
            s += __shfl_down_sync(0xffffffffu, s, off, 16);
        if (tx == 0) out[b0 + ty] = s + fc_b[0];
    }
}

extern "C" void kernel_launch(void* const* d_in, const int* in_sizes, int n_in,
                              void* d_out, int out_size)
{
    const float* x    = (const float*)d_in[0];
    const float* W_xh = (const float*)d_in[1];
    const float* W_hh = (const float*)d_in[2];
    const float* bias = (const float*)d_in[3];
    const float* fc_w = (const float*)d_in[4];
    const float* fc_b = (const float*)d_in[5];
    float* out = (float*)d_out;

    cudaFuncSetAttribute(rnn_persistent_kernel,
                         cudaFuncAttributeMaxDynamicSharedMemorySize, SMEM_BYTES);

    rnn_persistent_kernel<<<NCTAS, THREADS, SMEM_BYTES>>>(
        x, W_xh, W_hh, bias, fc_w, fc_b, out);
}

// round 3
// speedup vs baseline: 1.1334x; 1.1334x over previous
#include <cuda_runtime.h>
#include <math.h>

#define BATCH 256
#define TSTEPS 512
#define IDIM 64
#define HDIM 512
#define BB 16               // batch rows per CTA
#define BJ 64               // h columns per CTA
#define NBB 16              // batch groups
#define NJB 8               // j groups (= CTAs per batch-group barrier)
#define NCTAS (NBB * NJB)   // 128
#define THREADS 512
#define GROUP 8

// padded strides (floats) chosen so 8 distinct rows/LDS.128 are conflict-free
#define H2PAD 1028          // duplicated h row: 1024 + 4   (1028 % 32 == 4)
#define X2PAD 132           // duplicated x row: 128 + 4
#define PPAD  68

// smem layout (floats)
#define SM_WHH   0
#define SM_WXH   (SM_WHH + HDIM * BJ)        // 32768
#define SM_H2    (SM_WXH + IDIM * BJ)        // 36864
#define SM_X2    (SM_H2 + BB * H2PAD)        // 53312
#define SM_PART  (SM_X2 + BB * X2PAD)        // 55424
#define SM_FLOATS (SM_PART + BB * PPAD)      // 56512
#define SMEM_BYTES (SM_FLOATS * 4)           // 226048 B

// scratch: double-buffered hidden state + per-group barrier state (padded lines)
__device__ float    g_h[2][BATCH * HDIM];
__device__ unsigned g_cnt[NBB * 32];
__device__ unsigned g_gen[NBB * 32];

#define FMA2(acc, a, b) \
    asm("fma.rn.f32x2 %0, %1, %2, %0;" : "+l"(acc) : "l"(a), "l"(b))
#define PACKF2(d, lo, hi) \
    asm("mov.b64 %0, {%1, %2};" : "=l"(d) : "r"(__float_as_uint(lo)), "r"(__float_as_uint(hi)))
#define UNPACKF2(lo, hi, s) \
    { unsigned _a, _b; asm("mov.b64 {%0, %1}, %2;" : "=r"(_a), "=r"(_b) : "l"(s)); \
      lo = __uint_as_float(_a); hi = __uint_as_float(_b); }

__device__ __forceinline__ void group_sync(int bb) {
    __syncthreads();
    if (threadIdx.x == 0) {
        __threadfence();                              // release h writes
        unsigned old = *(volatile unsigned*)&g_gen[bb * 32];
        unsigned a = atomicAdd(&g_cnt[bb * 32], 1u);
        if (a == GROUP - 1) {
            g_cnt[bb * 32] = 0;
            __threadfence();
            atomicAdd(&g_gen[bb * 32], 1u);
        } else {
            while (*(volatile unsigned*)&g_gen[bb * 32] == old) __nanosleep(20);
        }
        __threadfence();                              // acquire
    }
    __syncthreads();
}

extern __shared__ float smem[];

__global__ void __launch_bounds__(THREADS, 1)
rnn_persistent_kernel(const float* __restrict__ x,
                      const float* __restrict__ W_xh,
                      const float* __restrict__ W_hh,
                      const float* __restrict__ bias,
                      const float* __restrict__ fc_w,
                      const float* __restrict__ fc_b,
                      float* __restrict__ out)
{
    float* s_Whh = smem + SM_WHH;
    float* s_Wxh = smem + SM_WXH;
    float* s_h2  = smem + SM_H2;
    float* s_x2  = smem + SM_X2;
    float* s_pt  = smem + SM_PART;

    const int tid  = threadIdx.x;
    const int kz   = tid >> 8;                 // K-split half: 0 or 1
    const int wid8 = (tid >> 5) & 7;           // warp within half
    const int lane = tid & 31;
    // warp composition: 4 tx-groups x 8 ty-rows  -> balanced smem dedup
    const int tx = (wid8 >> 1) * 4 + (lane >> 3);   // 0..15 (4 cols each)
    const int ty = (wid8 & 1) * 8 + (lane & 7);     // 0..15 (row)

    const int bb = blockIdx.x >> 3;
    const int jb = blockIdx.x & 7;
    const int b0 = bb * BB;
    const int j0 = jb * BJ;

    // ---- persistent weight tiles ----
    for (int idx = tid; idx < HDIM * BJ / 4; idx += THREADS) {
        int k = idx >> 4, c = idx & 15;
        ((float4*)s_Whh)[idx] = *(const float4*)&W_hh[k * HDIM + j0 + c * 4];
    }
    for (int idx = tid; idx < IDIM * BJ / 4; idx += THREADS) {
        int i = idx >> 4, c = idx & 15;
        ((float4*)s_Wxh)[idx] = *(const float4*)&W_xh[i * HDIM + j0 + c * 4];
    }

    unsigned long long bias01 = 0ull, bias23 = 0ull;
    if (kz == 0) {
        float4 bv = *(const float4*)&bias[j0 + tx * 4];
        PACKF2(bias01, bv.x, bv.y);
        PACKF2(bias23, bv.z, bv.w);
    }

    // ---- zero h_0 rows of this batch group (redundant across jb: benign) ----
    for (int idx = tid; idx < BB * HDIM / 4; idx += THREADS) {
        int r = idx >> 7, c = idx & 127;
        *(float4*)&g_h[0][(b0 + r) * HDIM + c * 4] = make_float4(0.f, 0.f, 0.f, 0.f);
    }
    group_sync(bb);

    int p = 0;
    for (int t = 0; t < TSTEPS; ++t) {
        // ---- stage x tile, duplicated pairs (16 x 64 -> 16 x 128) ----
        if (tid < 256) {
            int r = tid >> 4, c = tid & 15;
            float4 v = *(const float4*)&x[((b0 + r) * TSTEPS + t) * IDIM + c * 4];
            float* d = s_x2 + r * X2PAD + c * 8;
            *(float4*)d       = make_float4(v.x, v.x, v.y, v.y);
            *(float4*)(d + 4) = make_float4(v.z, v.z, v.w, v.w);
        }
        // ---- stage h tile, duplicated pairs (16 x 512 -> 16 x 1024), L2 reads ----
        {
            const float4* hsrc = (const float4*)g_h[p];
            #pragma unroll
            for (int i = 0; i < 4; i++) {
                int idx = tid + i * THREADS;          // 0..2047
                int r = idx >> 7, c = idx & 127;
                float4 v = __ldcg(&hsrc[(b0 + r) * (HDIM / 4) + c]);
                float* d = s_h2 + r * H2PAD + c * 8;
                *(float4*)d       = make_float4(v.x, v.x, v.y, v.y);
                *(float4*)(d + 4) = make_float4(v.z, v.z, v.w, v.w);
            }
        }
        __syncthreads();

        unsigned long long a01 = bias01, a23 = bias23;

        // ---- x projection, this half's k range [kz*32, kz*32+32) ----
        {
            const float* xrow = s_x2 + ty * X2PAD + kz * 64;   // duplicated index
            const float* wx   = s_Wxh + kz * 32 * BJ + tx * 4;
            #pragma unroll
            for (int k = 0; k < 32; k += 2) {
                ulonglong2 hp = *(const ulonglong2*)(xrow + 2 * k);
                ulonglong2 w0 = *(const ulonglong2*)(wx + (k    ) * BJ);
                ulonglong2 w1 = *(const ulonglong2*)(wx + (k + 1) * BJ);
                FMA2(a01, hp.x, w0.x); FMA2(a23, hp.x, w0.y);
                FMA2(a01, hp.y, w1.x); FMA2(a23, hp.y, w1.y);
            }
        }
        // ---- recurrence, this half's k range [kz*256, kz*256+256) ----
        {
            const float* hrow = s_h2 + ty * H2PAD + kz * 512;  // duplicated index
            const float* wh   = s_Whh + kz * 256 * BJ + tx * 4;
            #pragma unroll 4
            for (int k = 0; k < 256; k += 2) {
                ulonglong2 hp = *(const ulonglong2*)(hrow + 2 * k);
                ulonglong2 w0 = *(const ulonglong2*)(wh + (k    ) * BJ);
                ulonglong2 w1 = *(const ulonglong2*)(wh + (k + 1) * BJ);
                FMA2(a01, hp.x, w0.x); FMA2(a23, hp.x, w0.y);
                FMA2(a01, hp.y, w1.x); FMA2(a23, hp.y, w1.y);
            }
        }

        // ---- cross-half reduction + tanh + store ----
        if (kz == 1) {
            float p0, p1, p2, p3;
            UNPACKF2(p0, p1, a01);
            UNPACKF2(p2, p3, a23);
            *(float4*)(s_pt + ty * PPAD + tx * 4) = make_float4(p0, p1, p2, p3);
        }
        __syncthreads();
        if (kz == 0) {
            float4 q = *(const float4*)(s_pt + ty * PPAD + tx * 4);
            float r0, r1, r2, r3;
            UNPACKF2(r0, r1, a01);
            UNPACKF2(r2, r3, a23);
            float4 hn;
            hn.x = tanhf(r0 + q.x);
            hn.y = tanhf(r1 + q.y);
            hn.z = tanhf(r2 + q.z);
            hn.w = tanhf(r3 + q.w);
            *(float4*)&g_h[p ^ 1][(b0 + ty) * HDIM + j0 + tx * 4] = hn;
        }
        p ^= 1;
        group_sync(bb);
    }

    // ---- final projection: out[b] = h_final[b,:] . fc_w + fc_b ----
    if (jb == 0 && tid < 256) {
        const int ftx = tid & 15, fty = tid >> 4;
        const float4* hrow = (const float4*)&g_h[p][(b0 + fty) * HDIM];
        float s = 0.f;
        #pragma unroll
        for (int c = ftx; c < HDIM / 4; c += 16) {
            float4 hv = __ldcg(&hrow[c]);
            float4 wv = *(const float4*)&fc_w[c * 4];
            s += hv.x * wv.x + hv.y * wv.y + hv.z * wv.z + hv.w * wv.w;
        }
        #pragma unroll
        for (int off = 8; off; off >>= 1)
            s += __shfl_down_sync(0xffffffffu, s, off, 16);
        if (ftx == 0) out[b0 + fty] = s + fc_b[0];
    }
}

extern "C" void kernel_launch(void* const* d_in, const int* in_sizes, int n_in,
                              void* d_out, int out_size)
{
    const float* x    = (const float*)d_in[0];
    const float* W_xh = (const float*)d_in[1];
    const float* W_hh = (const float*)d_in[2];
    const float* bias = (const float*)d_in[3];
    const float* fc_w = (const float*)d_in[4];
    const float* fc_b = (const float*)d_in[5];
    float* out = (float*)d_out;

    cudaFuncSetAttribute(rnn_persistent_kernel,
                         cudaFuncAttributeMaxDynamicSharedMemorySize, SMEM_BYTES);

    rnn_persistent_kernel<<<NCTAS, THREADS, SMEM_BYTES>>>(
        x, W_xh, W_hh, bias, fc_w, fc_b, out);
}

// round 4
// speedup vs baseline: 1.1359x; 1.0022x over previous
#include <cuda_runtime.h>
#include <math.h>

#define BATCH 256
#define TSTEPS 512
#define IDIM 64
#define HDIM 512
#define BB 16               // batch rows per CTA
#define BJ 64               // h columns per CTA
#define NBB 16              // batch groups
#define NJB 8               // j groups (= CTAs per batch-group barrier)
#define NCTAS (NBB * NJB)   // 128
#define THREADS 512
#define GROUP 8

// padded strides (floats) chosen so 8 distinct rows/LDS.128 are conflict-free
#define H2PAD 1028          // duplicated h row: 1024 + 4   (1028 % 32 == 4)
#define X2PAD 132           // duplicated x row: 128 + 4
#define PPAD  68

// smem layout (floats)
#define SM_WHH   0
#define SM_WXH   (SM_WHH + HDIM * BJ)        // 32768
#define SM_H2    (SM_WXH + IDIM * BJ)        // 36864
#define SM_X2    (SM_H2 + BB * H2PAD)        // 53312
#define SM_PART  (SM_X2 + BB * X2PAD)        // 55424
#define SM_FLOATS (SM_PART + BB * PPAD)      // 56512
#define SMEM_BYTES (SM_FLOATS * 4)           // 226048 B

// scratch: double-buffered hidden state + per-group barrier state (padded lines)
__device__ float    g_h[2][BATCH * HDIM];
__device__ unsigned g_cnt[NBB * 32];
__device__ unsigned g_gen[NBB * 32];

#define FMA2(acc, a, b) \
    asm("fma.rn.f32x2 %0, %1, %2, %0;" : "+l"(acc) : "l"(a), "l"(b))
#define PACKF2(d, lo, hi) \
    asm("mov.b64 %0, {%1, %2};" : "=l"(d) : "r"(__float_as_uint(lo)), "r"(__float_as_uint(hi)))
#define UNPACKF2(lo, hi, s) \
    { unsigned _a, _b; asm("mov.b64 {%0, %1}, %2;" : "=r"(_a), "=r"(_b) : "l"(s)); \
      lo = __uint_as_float(_a); hi = __uint_as_float(_b); }

__device__ __forceinline__ void group_sync(int bb) {
    __syncthreads();
    if (threadIdx.x == 0) {
        __threadfence();                              // release h writes
        unsigned old = *(volatile unsigned*)&g_gen[bb * 32];
        unsigned a = atomicAdd(&g_cnt[bb * 32], 1u);
        if (a == GROUP - 1) {
            g_cnt[bb * 32] = 0;
            __threadfence();
            atomicAdd(&g_gen[bb * 32], 1u);
        } else {
            while (*(volatile unsigned*)&g_gen[bb * 32] == old) __nanosleep(20);
        }
        __threadfence();                              // acquire
    }
    __syncthreads();
}

extern __shared__ float smem[];

__global__ void __launch_bounds__(THREADS, 1)
rnn_persistent_kernel(const float* __restrict__ x,
                      const float* __restrict__ W_xh,
                      const float* __restrict__ W_hh,
                      const float* __restrict__ bias,
                      const float* __restrict__ fc_w,
                      const float* __restrict__ fc_b,
                      float* __restrict__ out)
{
    float* s_Whh = smem + SM_WHH;
    float* s_Wxh = smem + SM_WXH;
    float* s_h2  = smem + SM_H2;
    float* s_x2  = smem + SM_X2;
    float* s_pt  = smem + SM_PART;

    const int tid  = threadIdx.x;
    const int kz   = tid >> 8;                 // K-split half: 0 or 1
    const int wid8 = (tid >> 5) & 7;           // warp within half
    const int lane = tid & 31;
    // warp composition: 4 tx-groups x 8 ty-rows  -> balanced smem dedup
    const int tx = (wid8 >> 1) * 4 + (lane >> 3);   // 0..15 (4 cols each)
    const int ty = (wid8 & 1) * 8 + (lane & 7);     // 0..15 (row)

    const int bb = blockIdx.x >> 3;
    const int jb = blockIdx.x & 7;
    const int b0 = bb * BB;
    const int j0 = jb * BJ;

    // ---- persistent weight tiles ----
    for (int idx = tid; idx < HDIM * BJ / 4; idx += THREADS) {
        int k = idx >> 4, c = idx & 15;
        ((float4*)s_Whh)[idx] = *(const float4*)&W_hh[k * HDIM + j0 + c * 4];
    }
    for (int idx = tid; idx < IDIM * BJ / 4; idx += THREADS) {
        int i = idx >> 4, c = idx & 15;
        ((float4*)s_Wxh)[idx] = *(const float4*)&W_xh[i * HDIM + j0 + c * 4];
    }

    unsigned long long bias01 = 0ull, bias23 = 0ull;
    if (kz == 0) {
        float4 bv = *(const float4*)&bias[j0 + tx * 4];
        PACKF2(bias01, bv.x, bv.y);
        PACKF2(bias23, bv.z, bv.w);
    }

    // ---- zero h_0 rows of this batch group (redundant across jb: benign) ----
    for (int idx = tid; idx < BB * HDIM / 4; idx += THREADS) {
        int r = idx >> 7, c = idx & 127;
        *(float4*)&g_h[0][(b0 + r) * HDIM + c * 4] = make_float4(0.f, 0.f, 0.f, 0.f);
    }
    group_sync(bb);

    int p = 0;
    for (int t = 0; t < TSTEPS; ++t) {
        // ---- stage x tile, duplicated pairs (16 x 64 -> 16 x 128) ----
        if (tid < 256) {
            int r = tid >> 4, c = tid & 15;
            float4 v = *(const float4*)&x[((b0 + r) * TSTEPS + t) * IDIM + c * 4];
            float* d = s_x2 + r * X2PAD + c * 8;
            *(float4*)d       = make_float4(v.x, v.x, v.y, v.y);
            *(float4*)(d + 4) = make_float4(v.z, v.z, v.w, v.w);
        }
        // ---- stage h tile, duplicated pairs (16 x 512 -> 16 x 1024), L2 reads ----
        {
            const float4* hsrc = (const float4*)g_h[p];
            #pragma unroll
            for (int i = 0; i < 4; i++) {
                int idx = tid + i * THREADS;          // 0..2047
                int r = idx >> 7, c = idx & 127;
                float4 v = __ldcg(&hsrc[(b0 + r) * (HDIM / 4) + c]);
                float* d = s_h2 + r * H2PAD + c * 8;
                *(float4*)d       = make_float4(v.x, v.x, v.y, v.y);
                *(float4*)(d + 4) = make_float4(v.z, v.z, v.w, v.w);
            }
        }
        __syncthreads();

        unsigned long long a01 = bias01, a23 = bias23;

        // ---- x projection, this half's k range [kz*32, kz*32+32) ----
        {
            const float* xrow = s_x2 + ty * X2PAD + kz * 64;   // duplicated index
            const float* wx   = s_Wxh + kz * 32 * BJ + tx * 4;
            #pragma unroll
            for (int k = 0; k < 32; k += 2) {
                ulonglong2 hp = *(const ulonglong2*)(xrow + 2 * k);
                ulonglong2 w0 = *(const ulonglong2*)(wx + (k    ) * BJ);
                ulonglong2 w1 = *(const ulonglong2*)(wx + (k + 1) * BJ);
                FMA2(a01, hp.x, w0.x); FMA2(a23, hp.x, w0.y);
                FMA2(a01, hp.y, w1.x); FMA2(a23, hp.y, w1.y);
            }
        }
        // ---- recurrence, this half's k range [kz*256, kz*256+256) ----
        {
            const float* hrow = s_h2 + ty * H2PAD + kz * 512;  // duplicated index
            const float* wh   = s_Whh + kz * 256 * BJ + tx * 4;
            #pragma unroll 4
            for (int k = 0; k < 256; k += 2) {
                ulonglong2 hp = *(const ulonglong2*)(hrow + 2 * k);
                ulonglong2 w0 = *(const ulonglong2*)(wh + (k    ) * BJ);
                ulonglong2 w1 = *(const ulonglong2*)(wh + (k + 1) * BJ);
                FMA2(a01, hp.x, w0.x); FMA2(a23, hp.x, w0.y);
                FMA2(a01, hp.y, w1.x); FMA2(a23, hp.y, w1.y);
            }
        }

        // ---- cross-half reduction + tanh + store ----
        if (kz == 1) {
            float p0, p1, p2, p3;
            UNPACKF2(p0, p1, a01);
            UNPACKF2(p2, p3, a23);
            *(float4*)(s_pt + ty * PPAD + tx * 4) = make_float4(p0, p1, p2, p3);
        }
        __syncthreads();
        if (kz == 0) {
            float4 q = *(const float4*)(s_pt + ty * PPAD + tx * 4);
            float r0, r1, r2, r3;
            UNPACKF2(r0, r1, a01);
            UNPACKF2(r2, r3, a23);
            float4 hn;
            hn.x = tanhf(r0 + q.x);
            hn.y = tanhf(r1 + q.y);
            hn.z = tanhf(r2 + q.z);
            hn.w = tanhf(r3 + q.w);
            *(float4*)&g_h[p ^ 1][(b0 + ty) * HDIM + j0 + tx * 4] = hn;
        }
        p ^= 1;
        group_sync(bb);
    }

    // ---- final projection: out[b] = h_final[b,:] . fc_w + fc_b ----
    if (jb == 0 && tid < 256) {
        const int ftx = tid & 15, fty = tid >> 4;
        const float4* hrow = (const float4*)&g_h[p][(b0 + fty) * HDIM];
        float s = 0.f;
        #pragma unroll
        for (int c = ftx; c < HDIM / 4; c += 16) {
            float4 hv = __ldcg(&hrow[c]);
            float4 wv = *(const float4*)&fc_w[c * 4];
            s += hv.x * wv.x + hv.y * wv.y + hv.z * wv.z + hv.w * wv.w;
        }
        #pragma unroll
        for (int off = 8; off; off >>= 1)
            s += __shfl_down_sync(0xffffffffu, s, off, 16);
        if (ftx == 0) out[b0 + fty] = s + fc_b[0];
    }
}

extern "C" void kernel_launch(void* const* d_in, const int* in_sizes, int n_in,
                              void* d_out, int out_size)
{
    const float* x    = (const float*)d_in[0];
    const float* W_xh = (const float*)d_in[1];
    const float* W_hh = (const float*)d_in[2];
    const float* bias = (const float*)d_in[3];
    const float* fc_w = (const float*)d_in[4];
    const float* fc_b = (const float*)d_in[5];
    float* out = (float*)d_out;

    cudaFuncSetAttribute(rnn_persistent_kernel,
                         cudaFuncAttributeMaxDynamicSharedMemorySize, SMEM_BYTES);

    rnn_persistent_kernel<<<NCTAS, THREADS, SMEM_BYTES>>>(
        x, W_xh, W_hh, bias, fc_w, fc_b, out);
}

// round 6
// speedup vs baseline: 2.1577x; 1.8996x over previous
#include <cuda_runtime.h>
#include <cstdint>

#define BATCH 256
#define TSTEPS 512
#define IDIM 64
#define HDIM 512
#define KTOT 576            // 512 (h) + 64 (x)
#define TM 64               // batch rows per CTA
#define TN 32               // h cols per CTA
#define NBG 4               // batch groups
#define NJB 16              // j tiles
#define NCTAS 64
#define GROUP 16            // CTAs per barrier group
#define THREADS 256

#define ASTRIDE 580         // 576 + 4 ; 580 % 32 == 4 -> conflict-free frag LDS
#define RSTR 36             // reduction buffer col stride
#define RPLANE (TM * RSTR)  // 2304 floats per k-split plane

// smem byte offsets
#define SA_OFF   0                       // A tile: 64 x 580 u32 = 148480 B (also reduce buf)
#define SB_OFF   148480                  // B packed: 72 kb x 4 nf x 32 lane x 2 u32 = 73728 B
#define SBIAS_OFF 222208                 // 32 floats
#define SMEM_BYTES 222336

__device__ float    g_h[2][BATCH * HDIM];
__device__ unsigned g_cnt[NBG * 32];
__device__ unsigned g_gen[NBG * 32];

__device__ __forceinline__ uint32_t f2tf32(float v) {
    uint32_t u;
    asm("cvt.rna.tf32.f32 %0, %1;" : "=r"(u) : "f"(v));
    return u;
}

__device__ __forceinline__ void mma_tf32(float* c, uint32_t a0, uint32_t a1,
                                         uint32_t a2, uint32_t a3,
                                         uint32_t b0, uint32_t b1) {
    asm volatile(
        "mma.sync.aligned.m16n8k8.row.col.f32.tf32.tf32.f32 "
        "{%0,%1,%2,%3}, {%4,%5,%6,%7}, {%8,%9}, {%0,%1,%2,%3};"
        : "+f"(c[0]), "+f"(c[1]), "+f"(c[2]), "+f"(c[3])
        : "r"(a0), "r"(a1), "r"(a2), "r"(a3), "r"(b0), "r"(b1));
}

__device__ __forceinline__ float tanh_fast(float z) {
    float a = fminf(fmaxf(z, -20.f), 20.f);
    float e;
    asm("ex2.approx.f32 %0, %1;" : "=f"(e) : "f"(a * 2.8853900817779268f));
    float r;
    asm("rcp.approx.f32 %0, %1;" : "=f"(r) : "f"(e + 1.0f));
    return fmaf(-2.0f, r, 1.0f);
}

__device__ __forceinline__ void group_sync(int bg) {
    __syncthreads();
    if (threadIdx.x == 0) {
        __threadfence();
        unsigned old = *(volatile unsigned*)&g_gen[bg * 32];
        unsigned a = atomicAdd(&g_cnt[bg * 32], 1u);
        if (a == GROUP - 1) {
            g_cnt[bg * 32] = 0;
            __threadfence();
            atomicAdd(&g_gen[bg * 32], 1u);
        } else {
            while (*(volatile unsigned*)&g_gen[bg * 32] == old) __nanosleep(20);
        }
        __threadfence();
    }
    __syncthreads();
}

extern __shared__ char smem[];

__global__ void __launch_bounds__(THREADS, 1)
rnn_mma_kernel(const float* __restrict__ x,    const float* __restrict__ W_xh,
               const float* __restrict__ W_hh, const float* __restrict__ bias,
               const float* __restrict__ fc_w, const float* __restrict__ fc_b,
               float* __restrict__ out)
{
    uint32_t* sA   = (uint32_t*)(smem + SA_OFF);
    uint32_t* sB   = (uint32_t*)(smem + SB_OFF);
    float*    sRed = (float*)(smem + SA_OFF);       // reuse A region after mma
    float*    sBias = (float*)(smem + SBIAS_OFF);

    const int tid  = threadIdx.x;
    const int wid  = tid >> 5;
    const int lane = tid & 31;
    const int mw   = wid & 1;        // m half: rows mw*32..mw*32+31
    const int kw   = wid >> 1;       // k split: k-blocks [kw*18, kw*18+18)
    const int bg   = blockIdx.x >> 4;
    const int jb   = blockIdx.x & 15;
    const int m0   = bg * TM;        // global batch row base
    const int j0   = jb * TN;        // global h col base

    // ---- pack B = [W_hh ; W_xh]^T tile, frag-major, tf32 (once) ----
    for (int idx = tid; idx < TN * KTOT; idx += THREADS) {
        int n = idx & 31, k = idx >> 5;
        float w = (k < HDIM) ? W_hh[k * HDIM + j0 + n]
                             : W_xh[(k - HDIM) * HDIM + j0 + n];
        int kb = k >> 3, nf = n >> 3, n8 = n & 7, kq = k & 7;
        int fl = n8 * 4 + (kq & 3);
        sB[(((kb * 4 + nf) * 32 + fl) << 1) + (kq >> 2)] = f2tf32(w);
    }
    if (tid < TN) sBias[tid] = bias[j0 + tid];

    // ---- zero h_0 for this batch group (redundant across jb, identical) ----
    for (int idx = tid; idx < TM * HDIM / 4; idx += THREADS)
        ((float4*)g_h[0])[m0 * (HDIM / 4) + idx] =
            make_float4(0.f, 0.f, 0.f, 0.f);
    group_sync(bg);

    // per-warp A fragment base (row-major, padded stride)
    const uint32_t* Arow = sA + (mw * 32 + (lane >> 2)) * ASTRIDE + (lane & 3);
    const int kb0 = kw * 18;

    int p = 0;
    for (int t = 0; t < TSTEPS; ++t) {
        // ---- stage A = [h | x] rows, tf32-converted (64 x 576) ----
        {
            const float4* hp = (const float4*)g_h[p];
            const float4* xp = (const float4*)x;
            #pragma unroll
            for (int i = 0; i < 36; i++) {
                int idx = i * THREADS + tid;           // 0..9215
                int r = idx / 144, c4 = idx - r * 144; // 144 float4 per row
                float4 v = (c4 < 128)
                    ? __ldcg(&hp[(m0 + r) * (HDIM / 4) + c4])
                    : __ldg(&xp[((m0 + r) * TSTEPS + t) * (IDIM / 4) + (c4 - 128)]);
                uint4 u;
                u.x = f2tf32(v.x); u.y = f2tf32(v.y);
                u.z = f2tf32(v.z); u.w = f2tf32(v.w);
                *(uint4*)&sA[r * ASTRIDE + c4 * 4] = u;
            }
        }
        __syncthreads();

        // ---- mma phase: warp tile 32x32, K range = 18 k8-blocks ----
        float c[2][4][4];
        #pragma unroll
        for (int mf = 0; mf < 2; mf++)
            #pragma unroll
            for (int nf = 0; nf < 4; nf++)
                #pragma unroll
                for (int q = 0; q < 4; q++) c[mf][nf][q] = 0.f;

        #pragma unroll 6
        for (int kb = kb0; kb < kb0 + 18; kb++) {
            const uint32_t* ap = Arow + kb * 8;
            uint32_t a[2][4];
            #pragma unroll
            for (int mf = 0; mf < 2; mf++) {
                const uint32_t* am = ap + mf * (16 * ASTRIDE);
                a[mf][0] = am[0];
                a[mf][1] = am[8 * ASTRIDE];
                a[mf][2] = am[4];
                a[mf][3] = am[8 * ASTRIDE + 4];
            }
            const uint2* bp = (const uint2*)sB + (kb * 4) * 32 + lane;
            #pragma unroll
            for (int nf = 0; nf < 4; nf++) {
                uint2 bv = bp[nf * 32];
                mma_tf32(c[0][nf], a[0][0], a[0][1], a[0][2], a[0][3], bv.x, bv.y);
                mma_tf32(c[1][nf], a[1][0], a[1][1], a[1][2], a[1][3], bv.x, bv.y);
            }
        }
        __syncthreads();   // all warps done reading A -> safe to reuse as reduce buf

        // ---- store partials to reduce buffer [kw][row][col] ----
        {
            float* base = sRed + kw * RPLANE;
            #pragma unroll
            for (int mf = 0; mf < 2; mf++) {
                int r = mw * 32 + mf * 16 + (lane >> 2);
                #pragma unroll
                for (int nf = 0; nf < 4; nf++) {
                    int cc = nf * 8 + (lane & 3) * 2;
                    *(float2*)&base[r * RSTR + cc] =
                        make_float2(c[mf][nf][0], c[mf][nf][1]);
                    *(float2*)&base[(r + 8) * RSTR + cc] =
                        make_float2(c[mf][nf][2], c[mf][nf][3]);
                }
            }
        }
        __syncthreads();

        // ---- reduce 4 partials + bias + tanh + store h_next ----
        {
            int r = tid >> 2;
            int cb = (tid & 3) * 8;
            float4 s0 = make_float4(0.f, 0.f, 0.f, 0.f), s1 = s0;
            #pragma unroll
            for (int q = 0; q < 4; q++) {
                const float* b = sRed + q * RPLANE + r * RSTR + cb;
                float4 v0 = *(const float4*)b;
                float4 v1 = *(const float4*)(b + 4);
                s0.x += v0.x; s0.y += v0.y; s0.z += v0.z; s0.w += v0.w;
                s1.x += v1.x; s1.y += v1.y; s1.z += v1.z; s1.w += v1.w;
            }
            float4 bb0 = *(const float4*)&sBias[cb];
            float4 bb1 = *(const float4*)&sBias[cb + 4];
            float4 o0, o1;
            o0.x = tanh_fast(s0.x + bb0.x); o0.y = tanh_fast(s0.y + bb0.y);
            o0.z = tanh_fast(s0.z + bb0.z); o0.w = tanh_fast(s0.w + bb0.w);
            o1.x = tanh_fast(s1.x + bb1.x); o1.y = tanh_fast(s1.y + bb1.y);
            o1.z = tanh_fast(s1.z + bb1.z); o1.w = tanh_fast(s1.w + bb1.w);
            float* hd = &g_h[p ^ 1][(m0 + r) * HDIM + j0 + cb];
            *(float4*)hd = o0;
            *(float4*)(hd + 4) = o1;
        }
        p ^= 1;
        group_sync(bg);
    }

    // ---- final projection: out[b] = h . fc_w + fc_b (jb==0 CTAs) ----
    if (jb == 0) {
        const int row = m0 + (tid >> 2);
        const int q   = tid & 3;
        const float4* hr = (const float4*)&g_h[p][(int64_t)row * HDIM + q * 128];
        const float4* wr = (const float4*)&fc_w[q * 128];
        float s = 0.f;
        #pragma unroll 8
        for (int i = 0; i < 32; i++) {
            float4 a = __ldcg(&hr[i]);
            float4 b = wr[i];
            s += a.x * b.x + a.y * b.y + a.z * b.z + a.w * b.w;
        }
        s += __shfl_down_sync(0xffffffffu, s, 2, 4);
        s += __shfl_down_sync(0xffffffffu, s, 1, 4);
        if (q == 0) out[row] = s + fc_b[0];
    }
}

extern "C" void kernel_launch(void* const* d_in, const int* in_sizes, int n_in,
                              void* d_out, int out_size)
{
    const float* x    = (const float*)d_in[0];
    const float* W_xh = (const float*)d_in[1];
    const float* W_hh = (const float*)d_in[2];
    const float* bias = (const float*)d_in[3];
    const float* fc_w = (const float*)d_in[4];
    const float* fc_b = (const float*)d_in[5];
    float* out = (float*)d_out;

    cudaFuncSetAttribute(rnn_mma_kernel,
                         cudaFuncAttributeMaxDynamicSharedMemorySize, SMEM_BYTES);

    rnn_mma_kernel<<<NCTAS, THREADS, SMEM_BYTES>>>(
        x, W_xh, W_hh, bias, fc_w, fc_b, out);
}

// round 7
// speedup vs baseline: 3.3920x; 1.5720x over previous
#include <cuda_runtime.h>
#include <cstdint>

#define BATCH 256
#define TSTEPS 512
#define IDIM 64
#define HDIM 512
#define KTOT 576            // 512 (h) + 64 (x)
#define KB 72               // k8 blocks
#define TM 32               // batch rows per CTA
#define TN 32               // h cols per CTA
#define NBG 8
#define NJB 16
#define NCTAS 128
#define GROUP 16
#define THREADS 256

#define ASTRIDE 580         // floats per A row (580%32==4 -> conflict-free frags)
#define RSTR 36
#define RPLANE (TM * RSTR)  // 1152 floats per k-split plane

// smem byte offsets
#define SA_OFF    0         // A tile: 32 x 580 x 4 = 74240 B
#define SB_OFF    74240     // B packed: 72 kb x 4 nf x 32 lane x 8B = 73728 B
#define SRED_OFF  147968    // 4 planes x 1152 x 4 = 18432 B
#define SBIAS_OFF 166400    // 32 floats
#define SMEM_BYTES 166528

__device__ float    g_h[2][BATCH * HDIM];       // tf32-rounded bits stored as float
__device__ uint32_t g_xt[BATCH * TSTEPS * IDIM]; // x pre-converted to tf32 bits
__device__ unsigned g_cnt[NBG * 32];
__device__ unsigned g_gen[NBG * 32];
__device__ unsigned g_icnt, g_igen;

__device__ __forceinline__ uint32_t f2tf32(float v) {
    uint32_t u;
    asm("cvt.rna.tf32.f32 %0, %1;" : "=r"(u) : "f"(v));
    return u;
}
__device__ __forceinline__ void mma_tf32(float* c, const uint32_t* a,
                                         uint32_t b0, uint32_t b1) {
    asm volatile(
        "mma.sync.aligned.m16n8k8.row.col.f32.tf32.tf32.f32 "
        "{%0,%1,%2,%3}, {%4,%5,%6,%7}, {%8,%9}, {%0,%1,%2,%3};"
        : "+f"(c[0]), "+f"(c[1]), "+f"(c[2]), "+f"(c[3])
        : "r"(a[0]), "r"(a[1]), "r"(a[2]), "r"(a[3]), "r"(b0), "r"(b1));
}
#define CP16(dst, src) \
    asm volatile("cp.async.ca.shared.global [%0], [%1], 16;" \
                 :: "r"(dst), "l"(src) : "memory")
#define CP_COMMIT() asm volatile("cp.async.commit_group;" ::: "memory")
#define CP_WAIT0()  asm volatile("cp.async.wait_group 0;" ::: "memory")

__device__ __forceinline__ float tanh_fast(float z) {
    float a = fminf(fmaxf(z, -20.f), 20.f);
    float e;
    asm("ex2.approx.f32 %0, %1;" : "=f"(e) : "f"(a * 2.8853900817779268f));
    float r;
    asm("rcp.approx.f32 %0, %1;" : "=f"(r) : "f"(e + 1.0f));
    return fmaf(-2.0f, r, 1.0f);
}

__device__ __forceinline__ void barrier_core(unsigned* cnt, unsigned* gen, int n) {
    __threadfence();
    unsigned old = *(volatile unsigned*)gen;
    unsigned a = atomicAdd(cnt, 1u);
    if ((int)a == n - 1) {
        *cnt = 0;
        __threadfence();
        atomicAdd(gen, 1u);
    } else {
        while (*(volatile unsigned*)gen == old) __nanosleep(20);
    }
    __threadfence();
}
__device__ __forceinline__ void group_sync(int bg) {
    __syncthreads();
    if (threadIdx.x == 0) barrier_core(&g_cnt[bg * 32], &g_gen[bg * 32], GROUP);
    __syncthreads();
}
__device__ __forceinline__ void init_sync() {
    __syncthreads();
    if (threadIdx.x == 0) barrier_core(&g_icnt, &g_igen, NCTAS);
    __syncthreads();
}

extern __shared__ char smem[];

__global__ void __launch_bounds__(THREADS, 1)
rnn_mma_kernel(const float* __restrict__ x,    const float* __restrict__ W_xh,
               const float* __restrict__ W_hh, const float* __restrict__ bias,
               const float* __restrict__ fc_w, const float* __restrict__ fc_b,
               float* __restrict__ out)
{
    uint32_t* sB    = (uint32_t*)(smem + SB_OFF);
    float*    sRed  = (float*)(smem + SRED_OFF);
    float*    sBias = (float*)(smem + SBIAS_OFF);

    uint32_t sa_base;
    asm("{ .reg .u64 t; cvta.to.shared.u64 t, %1; cvt.u32.u64 %0, t; }"
        : "=r"(sa_base) : "l"(smem));

    const int tid  = threadIdx.x;
    const int wid  = tid >> 5;
    const int lane = tid & 31;
    const int nw   = wid & 1;        // n half: cols nw*16..nw*16+15
    const int kw   = wid >> 1;       // k split: kb [kw*18, kw*18+18)
    const int bg   = blockIdx.x >> 4;
    const int jb   = blockIdx.x & 15;
    const int m0   = bg * TM;
    const int j0   = jb * TN;

    // ---- pre-phase 1: convert all of x to tf32 bits (grid-stride) ----
    {
        const float4* xs = (const float4*)x;
        const int NX4 = BATCH * TSTEPS * IDIM / 4;
        for (int i = blockIdx.x * THREADS + tid; i < NX4; i += NCTAS * THREADS) {
            float4 v = xs[i];
            uint4 u;
            u.x = f2tf32(v.x); u.y = f2tf32(v.y);
            u.z = f2tf32(v.z); u.w = f2tf32(v.w);
            *(uint4*)&g_xt[i * 4] = u;
        }
    }
    // ---- pre-phase 2: zero h_0 rows of this bg (jb==0 CTAs only) ----
    if (jb == 0) {
        for (int i = tid; i < TM * HDIM / 4; i += THREADS)
            ((float4*)g_h[0])[m0 * (HDIM / 4) + i] =
                make_float4(0.f, 0.f, 0.f, 0.f);
    }
    // ---- pack B = [W_hh ; W_xh]^T tile, frag-major, tf32 (once) ----
    for (int idx = tid; idx < TN * KTOT; idx += THREADS) {
        int n = idx & 31, k = idx >> 5;
        float w = (k < HDIM) ? W_hh[k * HDIM + j0 + n]
                             : W_xh[(k - HDIM) * HDIM + j0 + n];
        int kb = k >> 3, nf = n >> 3, n8 = n & 7, kq = k & 7;
        int fl = n8 * 4 + (kq & 3);
        sB[(((kb * 4 + nf) * 32 + fl) << 1) + (kq >> 2)] = f2tf32(w);
    }
    if (tid < TN) sBias[tid] = bias[j0 + tid];
    init_sync();    // x-convert + h0 + B visible everywhere

    // per-warp A fragment base (row-major, padded stride), uint32 view
    const uint32_t* Au = (const uint32_t*)smem + (lane >> 2) * ASTRIDE + (lane & 3);
    const int kb0 = kw * 18;

    int p = 0;
    for (int t = 0; t < TSTEPS; ++t) {
        // ---- stage A = [h | x] (32 x 576 tf32 bits) via cp.async ----
        {
            const float4* hp = (const float4*)g_h[p];
            const uint4*  xp = (const uint4*)g_xt;
            int r = tid / 144, c4 = tid % 144;
            #pragma unroll
            for (int i = 0; i < 18; i++) {
                const void* src = (c4 < 128)
                    ? (const void*)&hp[(m0 + r) * 128 + c4]
                    : (const void*)&xp[((int64_t)(m0 + r) * TSTEPS + t) * 16 + (c4 - 128)];
                CP16(sa_base + r * (ASTRIDE * 4) + c4 * 16, src);
                r += 1; c4 += 112;
                if (c4 >= 144) { c4 -= 144; r += 1; }
            }
            CP_COMMIT();
            CP_WAIT0();
        }
        __syncthreads();

        // ---- mma: warp tile 32x16, K range = 18 k8-blocks ----
        float c[2][2][4];
        #pragma unroll
        for (int mf = 0; mf < 2; mf++)
            #pragma unroll
            for (int nf = 0; nf < 2; nf++)
                #pragma unroll
                for (int q = 0; q < 4; q++) c[mf][nf][q] = 0.f;

        #pragma unroll 6
        for (int kb = kb0; kb < kb0 + 18; kb++) {
            const uint32_t* ar = Au + kb * 8;
            uint32_t a[2][4];
            #pragma unroll
            for (int mf = 0; mf < 2; mf++) {
                const uint32_t* am = ar + mf * (16 * ASTRIDE);
                a[mf][0] = am[0];
                a[mf][1] = am[8 * ASTRIDE];
                a[mf][2] = am[4];
                a[mf][3] = am[8 * ASTRIDE + 4];
            }
            const uint2* bp = (const uint2*)sB + ((kb * 4 + nw * 2) * 32) + lane;
            uint2 b0 = bp[0], b1 = bp[32];
            mma_tf32(c[0][0], a[0], b0.x, b0.y);
            mma_tf32(c[0][1], a[0], b1.x, b1.y);
            mma_tf32(c[1][0], a[1], b0.x, b0.y);
            mma_tf32(c[1][1], a[1], b1.x, b1.y);
        }

        // ---- partial store to dedicated sRed[kw] ----
        {
            float* pl = sRed + kw * RPLANE;
            #pragma unroll
            for (int mf = 0; mf < 2; mf++) {
                int r = mf * 16 + (lane >> 2);
                #pragma unroll
                for (int nf = 0; nf < 2; nf++) {
                    int cb = nw * 16 + nf * 8 + (lane & 3) * 2;
                    *(float2*)&pl[r * RSTR + cb] =
                        make_float2(c[mf][nf][0], c[mf][nf][1]);
                    *(float2*)&pl[(r + 8) * RSTR + cb] =
                        make_float2(c[mf][nf][2], c[mf][nf][3]);
                }
            }
        }
        __syncthreads();

        // ---- reduce 4 planes + bias + tanh + tf32-round + store h_next ----
        {
            int r = tid >> 3;
            int cb = (tid & 7) * 4;
            float4 s = make_float4(0.f, 0.f, 0.f, 0.f);
            #pragma unroll
            for (int q = 0; q < 4; q++) {
                float4 v = *(const float4*)&sRed[q * RPLANE + r * RSTR + cb];
                s.x += v.x; s.y += v.y; s.z += v.z; s.w += v.w;
            }
            float4 bb = *(const float4*)&sBias[cb];
            uint4 u;
            u.x = f2tf32(tanh_fast(s.x + bb.x));
            u.y = f2tf32(tanh_fast(s.y + bb.y));
            u.z = f2tf32(tanh_fast(s.z + bb.z));
            u.w = f2tf32(tanh_fast(s.w + bb.w));
            *(uint4*)&g_h[p ^ 1][(m0 + r) * HDIM + j0 + cb] = u;
        }
        p ^= 1;
        group_sync(bg);
    }

    // ---- final projection: out[b] = h . fc_w + fc_b (jb==0 CTAs) ----
    if (jb == 0) {
        const int row = m0 + (tid >> 3);
        const int seg = tid & 7;
        const float4* hr = (const float4*)&g_h[p][(int64_t)row * HDIM + seg * 64];
        const float4* wr = (const float4*)&fc_w[seg * 64];
        float s = 0.f;
        #pragma unroll 8
        for (int i = 0; i < 16; i++) {
            float4 a = hr[i];
            float4 b = wr[i];
            s += a.x * b.x + a.y * b.y + a.z * b.z + a.w * b.w;
        }
        s += __shfl_down_sync(0xffffffffu, s, 4, 8);
        s += __shfl_down_sync(0xffffffffu, s, 2, 8);
        s += __shfl_down_sync(0xffffffffu, s, 1, 8);
        if (seg == 0) out[row] = s + fc_b[0];
    }
}

extern "C" void kernel_launch(void* const* d_in, const int* in_sizes, int n_in,
                              void* d_out, int out_size)
{
    const float* x    = (const float*)d_in[0];
    const float* W_xh = (const float*)d_in[1];
    const float* W_hh = (const float*)d_in[2];
    const float* bias = (const float*)d_in[3];
    const float* fc_w = (const float*)d_in[4];
    const float* fc_b = (const float*)d_in[5];
    float* out = (float*)d_out;

    cudaFuncSetAttribute(rnn_mma_kernel,
                         cudaFuncAttributeMaxDynamicSharedMemorySize, SMEM_BYTES);

    rnn_mma_kernel<<<NCTAS, THREADS, SMEM_BYTES>>>(
        x, W_xh, W_hh, bias, fc_w, fc_b, out);
}

// round 10
// speedup vs baseline: 3.7552x; 1.1071x over previous
#include <cuda_runtime.h>
#include <cstdint>

#define BATCH 256
#define TSTEPS 512
#define IDIM 64
#define HDIM 512
#define KTOT 576            // 512 (h) + 64 (x)
#define TM 32               // batch rows per CTA
#define TN 32               // h cols per CTA
#define NBG 8
#define NJB 16
#define NCTAS 128
#define THREADS 512

#define ASTRIDE 580         // floats per A row (580%32==4 -> conflict-free frags)
#define RSTR 36
#define RPLANE (TM * RSTR)  // 1152 floats per k-split plane

// smem byte offsets
#define SA_OFF    0         // A tile: 32 x 580 x 4 = 74240 B
#define SB_OFF    74240     // B packed: 72 kb x 4 nf x 32 lane x 8B = 73728 B
#define SRED_OFF  147968    // 8 planes x 1152 x 4 = 36864 B
#define SBIAS_OFF 184832    // 32 floats
#define SMEM_BYTES 184960

__device__ float    g_h[2][BATCH * HDIM];        // tf32-rounded bits as float
__device__ uint32_t g_xt[BATCH * TSTEPS * IDIM]; // x pre-converted to tf32 bits
__device__ unsigned g_flag[NBG * NJB * 32];      // per-CTA epoch flags (128B apart)
__device__ unsigned g_icnt, g_igen;              // init barrier (replay-safe)

__device__ __forceinline__ uint32_t f2tf32(float v) {
    uint32_t u;
    asm("cvt.rna.tf32.f32 %0, %1;" : "=r"(u) : "f"(v));
    return u;
}
__device__ __forceinline__ void mma_tf32(float* c, const uint32_t* a,
                                         uint32_t b0, uint32_t b1) {
    asm volatile(
        "mma.sync.aligned.m16n8k8.row.col.f32.tf32.tf32.f32 "
        "{%0,%1,%2,%3}, {%4,%5,%6,%7}, {%8,%9}, {%0,%1,%2,%3};"
        : "+f"(c[0]), "+f"(c[1]), "+f"(c[2]), "+f"(c[3])
        : "r"(a[0]), "r"(a[1]), "r"(a[2]), "r"(a[3]), "r"(b0), "r"(b1));
}
#define CPG16(dst, src) \
    asm volatile("cp.async.cg.shared.global [%0], [%1], 16;" \
                 :: "r"(dst), "l"(src) : "memory")
#define CP_COMMIT() asm volatile("cp.async.commit_group;" ::: "memory")
#define CP_WAIT0()  asm volatile("cp.async.wait_group 0;" ::: "memory")

__device__ __forceinline__ unsigned ld_acq(const unsigned* p) {
    unsigned v;
    asm volatile("ld.acquire.gpu.u32 %0, [%1];" : "=r"(v) : "l"(p) : "memory");
    return v;
}
__device__ __forceinline__ void st_rel(unsigned* p, unsigned v) {
    asm volatile("fence.acq_rel.gpu;" ::: "memory");
    asm volatile("st.relaxed.gpu.u32 [%0], %1;" :: "l"(p), "r"(v) : "memory");
}

__device__ __forceinline__ float tanh_fast(float z) {
    float a = fminf(fmaxf(z, -20.f), 20.f);
    float e;
    asm("ex2.approx.f32 %0, %1;" : "=f"(e) : "f"(a * 2.8853900817779268f));
    float r;
    asm("rcp.approx.f32 %0, %1;" : "=f"(r) : "f"(e + 1.0f));
    return fmaf(-2.0f, r, 1.0f);
}

__device__ __forceinline__ void init_sync() {
    __syncthreads();
    if (threadIdx.x == 0) {
        __threadfence();
        unsigned old = *(volatile unsigned*)&g_igen;
        unsigned a = atomicAdd(&g_icnt, 1u);
        if ((int)a == NCTAS - 1) {
            g_icnt = 0;
            __threadfence();
            atomicAdd(&g_igen, 1u);
        } else {
            while (*(volatile unsigned*)&g_igen == old) __nanosleep(32);
        }
        __threadfence();
    }
    __syncthreads();
}

extern __shared__ char smem[];

__global__ void __launch_bounds__(THREADS, 1)
rnn_mma_kernel(const float* __restrict__ x,    const float* __restrict__ W_xh,
               const float* __restrict__ W_hh, const float* __restrict__ bias,
               const float* __restrict__ fc_w, const float* __restrict__ fc_b,
               float* __restrict__ out)
{
    uint32_t* sB    = (uint32_t*)(smem + SB_OFF);
    float*    sRed  = (float*)(smem + SRED_OFF);
    float*    sBias = (float*)(smem + SBIAS_OFF);

    uint32_t sa_base;
    asm("{ .reg .u64 t; cvta.to.shared.u64 t, %1; cvt.u32.u64 %0, t; }"
        : "=r"(sa_base) : "l"(smem));

    const int tid  = threadIdx.x;
    const int wid  = tid >> 5;
    const int lane = tid & 31;
    const int nw   = wid & 1;        // n half: cols nw*16..+15
    const int kw   = wid >> 1;       // k split 0..7: kb [kw*9, kw*9+9)
    const int bg   = blockIdx.x >> 4;
    const int jb   = blockIdx.x & 15;
    const int m0   = bg * TM;
    const int j0   = jb * TN;

    // ---- pre-phase 1: convert all of x to tf32 bits (grid-stride) ----
    {
        const float4* xs = (const float4*)x;
        const int NX4 = BATCH * TSTEPS * IDIM / 4;
        for (int i = blockIdx.x * THREADS + tid; i < NX4; i += NCTAS * THREADS) {
            float4 v = xs[i];
            uint4 u;
            u.x = f2tf32(v.x); u.y = f2tf32(v.y);
            u.z = f2tf32(v.z); u.w = f2tf32(v.w);
            *(uint4*)&g_xt[i * 4] = u;
        }
    }
    // ---- pre-phase 2: zero h_0 rows of this bg (jb==0 CTAs only) ----
    if (jb == 0) {
        for (int i = tid; i < TM * HDIM / 4; i += THREADS)
            ((float4*)g_h[0])[m0 * (HDIM / 4) + i] =
                make_float4(0.f, 0.f, 0.f, 0.f);
    }
    // ---- pack B = [W_hh ; W_xh]^T tile, frag-major, tf32 (once) ----
    for (int idx = tid; idx < TN * KTOT; idx += THREADS) {
        int n = idx & 31, k = idx >> 5;
        float w = (k < HDIM) ? W_hh[k * HDIM + j0 + n]
                             : W_xh[(k - HDIM) * HDIM + j0 + n];
        int kb = k >> 3, nf = n >> 3, n8 = n & 7, kq = k & 7;
        int fl = n8 * 4 + (kq & 3);
        sB[(((kb * 4 + nf) * 32 + fl) << 1) + (kq >> 2)] = f2tf32(w);
    }
    if (tid < TN) sBias[tid] = bias[j0 + tid];

    // ---- read initial flag epochs (before anyone writes) ----
    unsigned F0p = 0, F0own = 0;
    if (tid < NJB) F0p = *(volatile unsigned*)&g_flag[(bg * NJB + tid) * 32];
    if (tid == 0)  F0own = *(volatile unsigned*)&g_flag[(bg * NJB + jb) * 32];
    init_sync();    // x-convert + h0 + B + F0 reads ordered before any step

    // per-warp A fragment base (uint32 view, padded stride)
    const uint32_t* Au = (const uint32_t*)smem + (lane >> 2) * ASTRIDE + (lane & 3);
    const int kb0 = kw * 9;

    int p = 0;
    for (int t = 0; t < TSTEPS; ++t) {
        // ---- stage x columns (independent of h flags): 1 cp.async/thread ----
        {
            const uint4* xp = (const uint4*)g_xt;
            int r = tid >> 4, c = tid & 15;
            CPG16(sa_base + r * (ASTRIDE * 4) + (128 + c) * 16,
                  &xp[((int64_t)(m0 + r) * TSTEPS + t) * 16 + c]);
            CP_COMMIT();
        }
        // ---- wait for this bg's producers to publish step-t h ----
        if (t > 0 && tid < NJB) {
            const unsigned* fp = &g_flag[(bg * NJB + tid) * 32];
            unsigned target = F0p + (unsigned)t;
            while ((int)(ld_acq(fp) - target) < 0) __nanosleep(16);
        }
        __syncthreads();
        // ---- stage h rows (32 x 128 float4): 8 cp.async/thread ----
        {
            const float4* hp = (const float4*)g_h[p];
            #pragma unroll
            for (int i = 0; i < 8; i++) {
                int idx = i * THREADS + tid;       // 0..4095
                int r = idx >> 7, c4 = idx & 127;
                CPG16(sa_base + r * (ASTRIDE * 4) + c4 * 16,
                      &hp[(m0 + r) * 128 + c4]);
            }
            CP_COMMIT();
            CP_WAIT0();
        }
        __syncthreads();

        // ---- mma: warp tile 32x16, K range = 9 k8-blocks ----
        float c[2][2][4];
        #pragma unroll
        for (int mf = 0; mf < 2; mf++)
            #pragma unroll
            for (int nf = 0; nf < 2; nf++)
                #pragma unroll
                for (int q = 0; q < 4; q++) c[mf][nf][q] = 0.f;

        #pragma unroll 3
        for (int kb = kb0; kb < kb0 + 9; kb++) {
            const uint32_t* ar = Au + kb * 8;
            uint32_t a[2][4];
            #pragma unroll
            for (int mf = 0; mf < 2; mf++) {
                const uint32_t* am = ar + mf * (16 * ASTRIDE);
                a[mf][0] = am[0];
                a[mf][1] = am[8 * ASTRIDE];
                a[mf][2] = am[4];
                a[mf][3] = am[8 * ASTRIDE + 4];
            }
            const uint2* bp = (const uint2*)sB + ((kb * 4 + nw * 2) * 32) + lane;
            uint2 b0 = bp[0], b1 = bp[32];
            mma_tf32(c[0][0], a[0], b0.x, b0.y);
            mma_tf32(c[0][1], a[0], b1.x, b1.y);
            mma_tf32(c[1][0], a[1], b0.x, b0.y);
            mma_tf32(c[1][1], a[1], b1.x, b1.y);
        }

        // ---- partial store to plane kw ----
        {
            float* pl = sRed + kw * RPLANE;
            #pragma unroll
            for (int mf = 0; mf < 2; mf++) {
                int r = mf * 16 + (lane >> 2);
                #pragma unroll
                for (int nf = 0; nf < 2; nf++) {
                    int cb = nw * 16 + nf * 8 + (lane & 3) * 2;
                    *(float2*)&pl[r * RSTR + cb] =
                        make_float2(c[mf][nf][0], c[mf][nf][1]);
                    *(float2*)&pl[(r + 8) * RSTR + cb] =
                        make_float2(c[mf][nf][2], c[mf][nf][3]);
                }
            }
        }
        __syncthreads();

        // ---- reduce 8 planes + bias + tanh + tf32-round + store h_next ----
        {
            int r  = tid >> 4;
            int cb = (tid & 15) * 2;
            float2 s = make_float2(0.f, 0.f);
            #pragma unroll
            for (int q = 0; q < 8; q++) {
                float2 v = *(const float2*)&sRed[q * RPLANE + r * RSTR + cb];
                s.x += v.x; s.y += v.y;
            }
            float2 bb = *(const float2*)&sBias[cb];
            uint2 u;
            u.x = f2tf32(tanh_fast(s.x + bb.x));
            u.y = f2tf32(tanh_fast(s.y + bb.y));
            *(uint2*)&g_h[p ^ 1][(m0 + r) * HDIM + j0 + cb] = u;
        }
        __syncthreads();
        if (tid == 0)
            st_rel(&g_flag[(bg * NJB + jb) * 32], F0own + (unsigned)(t + 1));
        p ^= 1;
    }

    // ---- FIX: wait for ALL producers' final (step-511) h before projection ----
    if (jb == 0) {
        if (tid < NJB) {
            const unsigned* fp = &g_flag[(bg * NJB + tid) * 32];
            unsigned target = F0p + (unsigned)TSTEPS;
            while ((int)(ld_acq(fp) - target) < 0) __nanosleep(16);
        }
        __syncthreads();

        // ---- final projection: out[b] = h . fc_w + fc_b ----
        const int row = m0 + (tid >> 4);
        const int seg = tid & 15;
        const float4* hr = (const float4*)&g_h[p][(int64_t)row * HDIM + seg * 32];
        const float4* wr = (const float4*)&fc_w[seg * 32];
        float s = 0.f;
        #pragma unroll
        for (int i = 0; i < 8; i++) {
            float4 a = __ldcg(&hr[i]);      // L2 read: bypass possibly-stale L1
            float4 b = wr[i];
            s += a.x * b.x + a.y * b.y + a.z * b.z + a.w * b.w;
        }
        s += __shfl_down_sync(0xffffffffu, s, 8, 16);
        s += __shfl_down_sync(0xffffffffu, s, 4, 16);
        s += __shfl_down_sync(0xffffffffu, s, 2, 16);
        s += __shfl_down_sync(0xffffffffu, s, 1, 16);
        if (seg == 0) out[row] = s + fc_b[0];
    }
}

extern "C" void kernel_launch(void* const* d_in, const int* in_sizes, int n_in,
                              void* d_out, int out_size)
{
    const float* x    = (const float*)d_in[0];
    const float* W_xh = (const float*)d_in[1];
    const float* W_hh = (const float*)d_in[2];
    const float* bias = (const float*)d_in[3];
    const float* fc_w = (const float*)d_in[4];
    const float* fc_b = (const float*)d_in[5];
    float* out = (float*)d_out;

    cudaFuncSetAttribute(rnn_mma_kernel,
                         cudaFuncAttributeMaxDynamicSharedMemorySize, SMEM_BYTES);

    rnn_mma_kernel<<<NCTAS, THREADS, SMEM_BYTES>>>(
        x, W_xh, W_hh, bias, fc_w, fc_b, out);
}